// round 14
// baseline (speedup 1.0000x reference)
#include <cuda_runtime.h>
#include <cuda_bf16.h>

#define C32 32
#define D8  8

typedef unsigned long long ull;

// ---- packed parameter block layout (floats) ----
//  [0,256)    M1T[d][i]
//  [256,288)  c1
//  [288,800)  G2A  (G2T cols 0..15, k-major: [k][0..15])
//  [800,832)  c2p
//  [832,864)  colsum
//  [864,896)  g2
//  [896,928)  be2
#define OFF_M1T 0
#define OFF_C1  256
#define OFF_G2A 288
#define OFF_C2P 800
#define OFF_COL 832
#define OFF_G2  864
#define OFF_BE2 896
#define PACK_N  928

__device__ __align__(16) float g_PACK[PACK_N];     // written by precompute
__device__ __align__(16) float g_G2B[C32 * 16];    // G2T cols 16..31 (smem path)

__constant__ __align__(16) float cPACK[PACK_N];    // single-memcpy constant mirror

// ---- packed f32x2 helpers (Blackwell FFMA2/FADD2/FMUL2, PTX-only) ----
__device__ __forceinline__ ull pk2(float lo, float hi) {
    ull r;
    asm("mov.b64 %0, {%1, %2};" : "=l"(r) : "f"(lo), "f"(hi));
    return r;
}
__device__ __forceinline__ void upk2(ull v, float& lo, float& hi) {
    asm("mov.b64 {%0, %1}, %2;" : "=f"(lo), "=f"(hi) : "l"(v));
}
__device__ __forceinline__ void fma2(ull& d, ull a, ull b) {
    asm("fma.rn.f32x2 %0, %1, %2, %0;" : "+l"(d) : "l"(a), "l"(b));
}
__device__ __forceinline__ void add2(ull& d, ull a) {
    asm("add.rn.f32x2 %0, %0, %1;" : "+l"(d) : "l"(a));
}
__device__ __forceinline__ void mul2(ull& d, ull a, ull b) {
    asm("mul.rn.f32x2 %0, %1, %2;" : "=l"(d) : "l"(a), "l"(b));
}

// ============================================================================
// Precompute: normalized adjacency folded into both layers, LN1 affine folded
// into layer 2 (derivation verified since R4). Writes the packed block.
// ============================================================================
__global__ void gnn_precompute_kernel(const float* __restrict__ adjacency,
                                      const float* __restrict__ W1,
                                      const float* __restrict__ b1,
                                      const float* __restrict__ W2,
                                      const float* __restrict__ b2,
                                      const float* __restrict__ g1,
                                      const float* __restrict__ be1,
                                      const float* __restrict__ g2,
                                      const float* __restrict__ be2) {
    __shared__ float A[C32][C32];
    __shared__ float dis[C32];
    __shared__ float Ms[C32][C32];   // M2T[k][i]
    __shared__ float Gs[C32][C32];   // G2T[k][i]
    int t = threadIdx.x;
    int i = t >> 5;
    int j = t & 31;

    float a = adjacency[i * C32 + j] + (i == j ? 1.0f : 0.0f);
    A[i][j] = a;
    __syncthreads();

    if (j == 0) {
        float s = 0.0f;
        #pragma unroll
        for (int k = 0; k < C32; k++) s += A[i][k];
        dis[i] = rsqrtf(s + 1e-6f);
    }
    __syncthreads();
    float na = dis[i] * A[i][j] * dis[j];
    __syncthreads();
    A[i][j] = na;   // A is now norm_adj
    __syncthreads();

    // M2T[k][i] for k = j
    {
        int k = j;
        float s = 0.0f;
        #pragma unroll
        for (int jj = 0; jj < C32; jj++) s += A[i][jj] * W2[jj * C32 + k];
        Ms[k][i] = s;
        float g = g1[k] * s;
        Gs[k][i] = g;
        if (i < 16) g_PACK[OFF_G2A + k * 16 + i] = g;
        else        g_G2B[k * 16 + (i - 16)] = g;
    }
    // M1T[d][i]
    if (t < C32 * D8) {
        int ii = t >> 3;
        int d  = t & 7;
        float s = 0.0f;
        #pragma unroll
        for (int jj = 0; jj < C32; jj++) s += A[ii][jj] * W1[jj * D8 + d];
        g_PACK[OFF_M1T + d * C32 + ii] = s;
    }
    // c1
    if (t < C32) {
        float s1 = 0.0f;
        #pragma unroll
        for (int jj = 0; jj < C32; jj++) s1 += A[t][jj] * b1[jj];
        g_PACK[OFF_C1 + t] = s1;
    }
    __syncthreads();

    // colsum, c2p, g2, be2
    if (t < C32) {
        float cs = 0.0f, cp = 0.0f, c2 = 0.0f;
        #pragma unroll
        for (int k = 0; k < C32; k++) {
            cs += Gs[k][t];
            cp += be1[k] * Ms[k][t];
            c2 += A[t][k] * b2[k];
        }
        g_PACK[OFF_COL + t] = cs;
        g_PACK[OFF_C2P + t] = c2 + cp;
        g_PACK[OFF_G2 + t]  = g2[t];
        g_PACK[OFF_BE2 + t] = be2[t];
    }
}

// ---- per-row helpers (split partial sums -> half-depth dependency chains) ----
__device__ __forceinline__ void relu_stats(ull* v, float& m, float& r) {
    ull sp0 = 0ULL, sp1 = 0ULL, ssp0 = 0ULL, ssp1 = 0ULL;
    #pragma unroll
    for (int i = 0; i < 16; i += 2) {
        float lo, hi;
        upk2(v[i], lo, hi);
        lo = fmaxf(lo, 0.0f);
        hi = fmaxf(hi, 0.0f);
        v[i] = pk2(lo, hi);
        add2(sp0, v[i]);
        fma2(ssp0, v[i], v[i]);
        upk2(v[i + 1], lo, hi);
        lo = fmaxf(lo, 0.0f);
        hi = fmaxf(hi, 0.0f);
        v[i + 1] = pk2(lo, hi);
        add2(sp1, v[i + 1]);
        fma2(ssp1, v[i + 1], v[i + 1]);
    }
    add2(sp0, sp1);
    add2(ssp0, ssp1);
    float s0, s1, q0, q1;
    upk2(sp0, s0, s1); upk2(ssp0, q0, q1);
    m = (s0 + s1) * (1.0f / 32.0f);
    float vv = (q0 + q1) * (1.0f / 32.0f) - m * m;
    r = rsqrtf(vv + 1e-5f);
}

__device__ __forceinline__ void fold_ln1(ull* acc, float m, float r) {
    ull nm = pk2(-m, -m);
    ull rp = pk2(r, r);
    const ulonglong2* cv = reinterpret_cast<const ulonglong2*>(cPACK + OFF_C2P);
    const ulonglong2* kv = reinterpret_cast<const ulonglong2*>(cPACK + OFF_COL);
    #pragma unroll
    for (int q = 0; q < 8; q++) {
        ulonglong2 cc = cv[q];
        ulonglong2 kk = kv[q];
        fma2(acc[2*q],   nm, kk.x);
        fma2(acc[2*q+1], nm, kk.y);
        ull t0 = cc.x; fma2(t0, rp, acc[2*q]);   acc[2*q]   = t0;
        ull t1 = cc.y; fma2(t1, rp, acc[2*q+1]); acc[2*q+1] = t1;
    }
}

__device__ __forceinline__ void epilogue_stage(ull* acc, float m2, float r2,
                                               float* buf) {
    ull r2p  = pk2(r2, r2);
    ull mr2p = pk2(-m2 * r2, -m2 * r2);
    const ulonglong2* gv = reinterpret_cast<const ulonglong2*>(cPACK + OFF_G2);
    const ulonglong2* bv = reinterpret_cast<const ulonglong2*>(cPACK + OFF_BE2);
    #pragma unroll
    for (int q = 0; q < 8; q++) {
        ulonglong2 gg = gv[q];
        ulonglong2 bb = bv[q];
        ull w0, w1;
        mul2(w0, gg.x, r2p);
        mul2(w1, gg.y, r2p);
        ull o0 = bb.x; fma2(o0, mr2p, gg.x); fma2(o0, acc[2*q],   w0);
        ull o1 = bb.y; fma2(o1, mr2p, gg.y); fma2(o1, acc[2*q+1], w1);
        float a0, a1, a2, a3;
        upk2(o0, a0, a1);
        upk2(o1, a2, a3);
        *reinterpret_cast<float4*>(buf + q * 4) = make_float4(a0, a1, a2, a3);
    }
}

// ============================================================================
// Main fused kernel (R7/R13 architecture, measured-best) with a 128-register
// cap (__launch_bounds__(128, 4)) -> 4 blocks/SM, 16 warps, occ 25%.
// 128 threads/block, 2 rows/thread. Layer-2 matrix split: cols 0..15 via
// constant port (LDC), cols 16..31 via smem crossbar (LDS). Coalesced stores
// via padded warp-local smem transpose.
// ============================================================================
__global__ __launch_bounds__(128, 4) void gnn_main_kernel(
    const float* __restrict__ x,
    float* __restrict__ out, int nrows) {

    __shared__ __align__(16) float sG2B[C32 * 16];
    __shared__ __align__(16) float stg[4][32 * 36];   // per-warp staging, pitch 36

    int t = threadIdx.x;
    ((float4*)sG2B)[t] = ((const float4*)g_G2B)[t];   // 512 floats = 128 float4
    __syncthreads();

    int w = t >> 5, l = t & 31;
    int rowA = blockIdx.x * 256 + t;
    int rowB = rowA + 128;
    bool actA = (rowA < nrows);
    bool actB = (rowB < nrows);

    ull ha[16], hb[16];   // layer1 accum / relu'd u
    ull aa[16], ab[16];   // layer2 accum

    // ---- load x rows ----
    float xra[8] = {0,0,0,0,0,0,0,0}, xrb[8] = {0,0,0,0,0,0,0,0};
    if (actA) {
        const float4* xv = reinterpret_cast<const float4*>(x + (size_t)rowA * D8);
        float4 a0 = xv[0], a1 = xv[1];
        xra[0]=a0.x; xra[1]=a0.y; xra[2]=a0.z; xra[3]=a0.w;
        xra[4]=a1.x; xra[5]=a1.y; xra[6]=a1.z; xra[7]=a1.w;
    }
    if (actB) {
        const float4* xv = reinterpret_cast<const float4*>(x + (size_t)rowB * D8);
        float4 b0 = xv[0], b1 = xv[1];
        xrb[0]=b0.x; xrb[1]=b0.y; xrb[2]=b0.z; xrb[3]=b0.w;
        xrb[4]=b1.x; xrb[5]=b1.y; xrb[6]=b1.z; xrb[7]=b1.w;
    }

    // ---- layer 1 (matrix + bias from constant port) ----
    {
        const ulonglong2* cv = reinterpret_cast<const ulonglong2*>(cPACK + OFF_C1);
        #pragma unroll
        for (int q = 0; q < 8; q++) {
            ulonglong2 c = cv[q];
            ha[2*q] = c.x; ha[2*q+1] = c.y;
            hb[2*q] = c.x; hb[2*q+1] = c.y;
        }
    }
    #pragma unroll
    for (int d = 0; d < D8; d++) {
        ull adA = pk2(xra[d], xra[d]);
        ull adB = pk2(xrb[d], xrb[d]);
        const ulonglong2* mr = reinterpret_cast<const ulonglong2*>(cPACK + OFF_M1T + d * C32);
        #pragma unroll
        for (int q = 0; q < 8; q++) {
            ulonglong2 mm = mr[q];
            fma2(ha[2*q],   adA, mm.x);
            fma2(ha[2*q+1], adA, mm.y);
            fma2(hb[2*q],   adB, mm.x);
            fma2(hb[2*q+1], adB, mm.y);
        }
    }

    // ---- relu + LN1 stats ----
    float mA, rA, mB, rB;
    relu_stats(ha, mA, rA);
    relu_stats(hb, mB, rB);

    // ---- layer 2: cols 0..15 from constant (acc[0..7]),
    //               cols 16..31 from smem (acc[8..15]) ----
    #pragma unroll
    for (int i = 0; i < 16; i++) { aa[i] = 0ULL; ab[i] = 0ULL; }
    #pragma unroll
    for (int p = 0; p < 16; p++) {
        float u0A, u1A, u0B, u1B;
        upk2(ha[p], u0A, u1A);
        upk2(hb[p], u0B, u1B);
        ull a0A = pk2(u0A, u0A), a1A = pk2(u1A, u1A);
        ull a0B = pk2(u0B, u0B), a1B = pk2(u1B, u1B);
        const ulonglong2* ca0 = reinterpret_cast<const ulonglong2*>(cPACK + OFF_G2A + (2*p)   * 16);
        const ulonglong2* ca1 = reinterpret_cast<const ulonglong2*>(cPACK + OFF_G2A + (2*p+1) * 16);
        const ulonglong2* sb0 = reinterpret_cast<const ulonglong2*>(sG2B + (2*p)   * 16);
        const ulonglong2* sb1 = reinterpret_cast<const ulonglong2*>(sG2B + (2*p+1) * 16);
        #pragma unroll
        for (int q = 0; q < 4; q++) {
            ulonglong2 m0 = ca0[q];
            fma2(aa[2*q],   a0A, m0.x);
            fma2(aa[2*q+1], a0A, m0.y);
            fma2(ab[2*q],   a0B, m0.x);
            fma2(ab[2*q+1], a0B, m0.y);
            ulonglong2 s0 = sb0[q];
            fma2(aa[8+2*q],   a0A, s0.x);
            fma2(aa[8+2*q+1], a0A, s0.y);
            fma2(ab[8+2*q],   a0B, s0.x);
            fma2(ab[8+2*q+1], a0B, s0.y);
        }
        #pragma unroll
        for (int q = 0; q < 4; q++) {
            ulonglong2 m1 = ca1[q];
            fma2(aa[2*q],   a1A, m1.x);
            fma2(aa[2*q+1], a1A, m1.y);
            fma2(ab[2*q],   a1B, m1.x);
            fma2(ab[2*q+1], a1B, m1.y);
            ulonglong2 s1 = sb1[q];
            fma2(aa[8+2*q],   a1A, s1.x);
            fma2(aa[8+2*q+1], a1A, s1.y);
            fma2(ab[8+2*q],   a1B, s1.x);
            fma2(ab[8+2*q+1], a1B, s1.y);
        }
    }

    // ---- fold LN1, relu + LN2 ----
    fold_ln1(aa, mA, rA);
    fold_ln1(ab, mB, rB);

    float m2A, r2A, m2B, r2B;
    relu_stats(aa, m2A, r2A);
    relu_stats(ab, m2B, r2B);

    float* buf = &stg[w][l * 36];
    const float* wb = &stg[w][0];

    // --- tile A: epilogue + coalesced store via padded smem transpose ---
    if (actA) epilogue_stage(aa, m2A, r2A, buf);
    __syncwarp();
    {
        int rowbase = blockIdx.x * 256 + w * 32;
        float4* odst = reinterpret_cast<float4*>(out + (size_t)rowbase * C32);
        #pragma unroll
        for (int q = 0; q < 8; q++) {
            int idx4 = l + q * 32;
            int rr = idx4 >> 3;
            int c4 = idx4 & 7;
            if (rowbase + rr < nrows) {
                float4 v = *reinterpret_cast<const float4*>(wb + rr * 36 + c4 * 4);
                odst[idx4] = v;
            }
        }
    }
    __syncwarp();

    // --- tile B (reuse buffer) ---
    if (actB) epilogue_stage(ab, m2B, r2B, buf);
    __syncwarp();
    {
        int rowbase = blockIdx.x * 256 + 128 + w * 32;
        float4* odst = reinterpret_cast<float4*>(out + (size_t)rowbase * C32);
        #pragma unroll
        for (int q = 0; q < 8; q++) {
            int idx4 = l + q * 32;
            int rr = idx4 >> 3;
            int c4 = idx4 & 7;
            if (rowbase + rr < nrows) {
                float4 v = *reinterpret_cast<const float4*>(wb + rr * 36 + c4 * 4);
                odst[idx4] = v;
            }
        }
    }
}

extern "C" void kernel_launch(void* const* d_in, const int* in_sizes, int n_in,
                              void* d_out, int out_size) {
    const float* x         = (const float*)d_in[0];
    const float* adjacency = (const float*)d_in[1];
    const float* W1        = (const float*)d_in[2];
    const float* b1        = (const float*)d_in[3];
    const float* W2        = (const float*)d_in[4];
    const float* b2        = (const float*)d_in[5];
    const float* g1        = (const float*)d_in[6];
    const float* be1       = (const float*)d_in[7];
    const float* g2        = (const float*)d_in[8];
    const float* be2       = (const float*)d_in[9];
    float* out = (float*)d_out;

    int nrows = in_sizes[0] / D8;  // B*TF*C rows of D=8

    gnn_precompute_kernel<<<1, 1024>>>(adjacency, W1, b1, W2, b2, g1, be1, g2, be2);

    // ONE constant-memory copy for the whole packed parameter block
    // (D2D async memcpy; graph-capturable node).
    void* pPACK;
    cudaGetSymbolAddress(&pPACK, g_PACK);
    cudaMemcpyToSymbolAsync(cPACK, pPACK, PACK_N * sizeof(float), 0,
                            cudaMemcpyDeviceToDevice, 0);

    int blocks = (nrows + 255) / 256;   // 256 rows per block (2 per thread)
    gnn_main_kernel<<<blocks, 128>>>(x, out, nrows);
}